// round 1
// baseline (speedup 1.0000x reference)
#include <cuda_runtime.h>
#include <math.h>

#define MAXN 20000
#define MAXE 320000

// ---------------- device scratch (no allocs allowed) ----------------
__device__ int   g_is64;
__device__ int   g_src[MAXE];
__device__ int   g_dst[MAXE];
__device__ int   g_esrc[MAXE];
__device__ float g_ewn[MAXE];
__device__ float g_deg[MAXN];
__device__ float g_dinv[MAXN];
__device__ int   g_cnt[MAXN];
__device__ int   g_rowptr[MAXN + 1];
__device__ int   g_cursor[MAXN];
__device__ float g_Phc[MAXN * 256];          // [P_h | P_c]
__device__ float g_base[(long long)MAXN * 512];
__device__ float g_h[MAXN * 128];
__device__ float g_c[MAXN * 128];
__device__ float g_z[MAXN * 128];

// ---------------- setup kernels ----------------
__global__ void k_init(int n) {
    int i = blockIdx.x * blockDim.x + threadIdx.x;
    if (i < n) { g_deg[i] = 0.f; g_cnt[i] = 0; }
    if (i == 0) g_is64 = 1;
}

// int64 values < 2^31 have zero high words; int32 edge data has random values
// at odd word positions. 128 odd words all zero => int64.
__global__ void k_detect(const unsigned int* __restrict__ w) {
    unsigned int v = w[2 * threadIdx.x + 1];
    if (v != 0u) g_is64 = 0;
}

__global__ void k_build(const void* __restrict__ ei, const float* __restrict__ ea, int E) {
    int e = blockIdx.x * blockDim.x + threadIdx.x;
    if (e >= E) return;
    int s, d;
    if (g_is64) {
        const long long* p = (const long long*)ei;
        s = (int)p[e]; d = (int)p[E + e];
    } else {
        const int* p = (const int*)ei;
        s = p[e]; d = p[E + e];
    }
    g_src[e] = s; g_dst[e] = d;
    atomicAdd(&g_deg[d], ea[e]);
    atomicAdd(&g_cnt[d], 1);
}

__global__ void k_dinv(int n) {
    int i = blockIdx.x * blockDim.x + threadIdx.x;
    if (i < n) g_dinv[i] = rsqrtf(g_deg[i] + 1.0f);
}

// single-block exclusive scan of g_cnt -> g_rowptr, g_cursor
__global__ void k_scan(int n) {
    __shared__ int s[1024];
    __shared__ int carry;
    if (threadIdx.x == 0) carry = 0;
    __syncthreads();
    for (int base = 0; base < n; base += 1024) {
        int i = base + threadIdx.x;
        int v = (i < n) ? g_cnt[i] : 0;
        s[threadIdx.x] = v;
        __syncthreads();
        for (int off = 1; off < 1024; off <<= 1) {
            int t = (threadIdx.x >= off) ? s[threadIdx.x - off] : 0;
            __syncthreads();
            s[threadIdx.x] += t;
            __syncthreads();
        }
        if (i < n) {
            int ex = carry + s[threadIdx.x] - v;
            g_rowptr[i] = ex;
            g_cursor[i] = ex;
        }
        __syncthreads();
        if (threadIdx.x == 0) carry += s[1023];
        __syncthreads();
    }
    if (threadIdx.x == 0) g_rowptr[n] = carry;
}

__global__ void k_scatter(const float* __restrict__ ea, int E) {
    int e = blockIdx.x * blockDim.x + threadIdx.x;
    if (e >= E) return;
    int s = g_src[e], d = g_dst[e];
    int pos = atomicAdd(&g_cursor[d], 1);
    g_esrc[pos] = s;
    g_ewn[pos] = g_dinv[s] * ea[e] * g_dinv[d];
}

// ---------------- sparse propagate: out[v] = sum_{e: dst=v} w_e * x[src_e] + dinv[v]^2 * x[v]
// one warp per node, 4 floats per lane (128 cols)
__global__ void k_prop(const float* __restrict__ x, int ldx,
                       float* __restrict__ out, int ldo, int n) {
    int v = (blockIdx.x * blockDim.x + threadIdx.x) >> 5;
    int lane = threadIdx.x & 31;
    if (v >= n) return;
    int beg = g_rowptr[v], end = g_rowptr[v + 1];
    float ax = 0.f, ay = 0.f, az = 0.f, aw = 0.f;
    for (int e = beg; e < end; e++) {
        int s = g_esrc[e];
        float wt = g_ewn[e];
        float4 vv = __ldg((const float4*)(x + (long long)s * ldx) + lane);
        ax = fmaf(wt, vv.x, ax); ay = fmaf(wt, vv.y, ay);
        az = fmaf(wt, vv.z, az); aw = fmaf(wt, vv.w, aw);
    }
    float di = g_dinv[v];
    float w2 = di * di;
    float4 vv = __ldg((const float4*)(x + (long long)v * ldx) + lane);
    ax = fmaf(w2, vv.x, ax); ay = fmaf(w2, vv.y, ay);
    az = fmaf(w2, vv.z, az); aw = fmaf(w2, vv.w, aw);
    float4 o; o.x = ax; o.y = ay; o.z = az; o.w = aw;
    *((float4*)(out + (long long)v * ldo) + lane) = o;
}

__device__ __forceinline__ float sigf(float x) { return 1.f / (1.f + expf(-x)); }

// ---------------- init GEMM: states = elu(Phc[N,256] @ W_init[256,256] + b_init)
// h = states[:,:128], c = states[:,128:]
__global__ void __launch_bounds__(256, 2) k_gemm_init(const float* __restrict__ W,
                                                      const float* __restrict__ b, int n) {
    __shared__ float xs[32][17];
    __shared__ float ws[16][256];
    const int row0 = blockIdx.x * 32;
    const int tx = threadIdx.x & 31;
    const int ty = threadIdx.x >> 5;
    float acc[4][8];
#pragma unroll
    for (int i = 0; i < 4; i++)
#pragma unroll
        for (int j = 0; j < 8; j++) acc[i][j] = 0.f;

    for (int k0 = 0; k0 < 256; k0 += 16) {
        for (int i = threadIdx.x; i < 16 * 64; i += 256) {
            int r = i >> 6, c4 = i & 63;
            float4 v = __ldg((const float4*)(W + (long long)(k0 + r) * 256) + c4);
            *(float4*)&ws[r][c4 * 4] = v;
        }
        if (threadIdx.x < 128) {
            int r = threadIdx.x >> 2, c4 = threadIdx.x & 3;
            int gr = row0 + r;
            float4 v = make_float4(0.f, 0.f, 0.f, 0.f);
            if (gr < n) v = __ldg((const float4*)(g_Phc + (long long)gr * 256 + k0) + c4);
            xs[r][c4 * 4 + 0] = v.x; xs[r][c4 * 4 + 1] = v.y;
            xs[r][c4 * 4 + 2] = v.z; xs[r][c4 * 4 + 3] = v.w;
        }
        __syncthreads();
#pragma unroll
        for (int k = 0; k < 16; k++) {
            float zr[4], wv[8];
#pragma unroll
            for (int i = 0; i < 4; i++) zr[i] = xs[ty + 8 * i][k];
#pragma unroll
            for (int j = 0; j < 8; j++) wv[j] = ws[k][tx + 32 * j];
#pragma unroll
            for (int i = 0; i < 4; i++)
#pragma unroll
                for (int j = 0; j < 8; j++) acc[i][j] = fmaf(zr[i], wv[j], acc[i][j]);
        }
        __syncthreads();
    }
#pragma unroll
    for (int i = 0; i < 4; i++) {
        int r = row0 + ty + 8 * i;
        if (r >= n) continue;
#pragma unroll
        for (int j = 0; j < 8; j++) {
            int col = tx + 32 * j;
            float v = acc[i][j] + b[col];
            v = (v > 0.f) ? v : expm1f(v);
            if (col < 128) g_h[(long long)r * 128 + col] = v;
            else           g_c[(long long)r * 128 + (col - 128)] = v;
        }
    }
}

// ---------------- main GEMM: [n,128] @ W[128,512]
// mode 0: out512 = acc + bias(aux[512])          (base precompute)
// mode 1: cc = acc + base(aux[n*512]); LSTM gates; update g_h/g_c; write oseq
__global__ void __launch_bounds__(256, 2) k_gemm512(const float* __restrict__ X, int ldx,
                                                    const float* __restrict__ W,
                                                    const float* __restrict__ aux,
                                                    float* __restrict__ o512,
                                                    float* __restrict__ oseq,
                                                    int n, int mode) {
    __shared__ float xs[32][17];
    __shared__ float ws[16][512];
    const int row0 = blockIdx.x * 32;
    const int tx = threadIdx.x & 31;
    const int ty = threadIdx.x >> 5;
    float acc[4][16];
#pragma unroll
    for (int i = 0; i < 4; i++)
#pragma unroll
        for (int j = 0; j < 16; j++) acc[i][j] = 0.f;

    for (int k0 = 0; k0 < 128; k0 += 16) {
        for (int i = threadIdx.x; i < 16 * 128; i += 256) {
            int r = i >> 7, c4 = i & 127;
            float4 v = __ldg((const float4*)(W + (long long)(k0 + r) * 512) + c4);
            *(float4*)&ws[r][c4 * 4] = v;
        }
        if (threadIdx.x < 128) {
            int r = threadIdx.x >> 2, c4 = threadIdx.x & 3;
            int gr = row0 + r;
            float4 v = make_float4(0.f, 0.f, 0.f, 0.f);
            if (gr < n) v = __ldg((const float4*)(X + (long long)gr * ldx + k0) + c4);
            xs[r][c4 * 4 + 0] = v.x; xs[r][c4 * 4 + 1] = v.y;
            xs[r][c4 * 4 + 2] = v.z; xs[r][c4 * 4 + 3] = v.w;
        }
        __syncthreads();
#pragma unroll
        for (int k = 0; k < 16; k++) {
            float zr[4], wv[16];
#pragma unroll
            for (int i = 0; i < 4; i++) zr[i] = xs[ty + 8 * i][k];
#pragma unroll
            for (int j = 0; j < 16; j++) wv[j] = ws[k][tx + 32 * j];
#pragma unroll
            for (int i = 0; i < 4; i++)
#pragma unroll
                for (int j = 0; j < 16; j++) acc[i][j] = fmaf(zr[i], wv[j], acc[i][j]);
        }
        __syncthreads();
    }

    if (mode == 0) {
#pragma unroll
        for (int i = 0; i < 4; i++) {
            int r = row0 + ty + 8 * i;
            if (r >= n) continue;
#pragma unroll
            for (int j = 0; j < 16; j++) {
                int col = tx + 32 * j;
                o512[(long long)r * 512 + col] = acc[i][j] + aux[col];
            }
        }
    } else {
#pragma unroll
        for (int i = 0; i < 4; i++) {
            int r = row0 + ty + 8 * i;
            if (r >= n) continue;
            const float* brow = aux + (long long)r * 512;
#pragma unroll
            for (int jj = 0; jj < 4; jj++) {
                int col = tx + 32 * jj;
                float iv = acc[i][jj]      + brow[col];
                float fv = acc[i][4 + jj]  + brow[128 + col];
                float ov = acc[i][8 + jj]  + brow[256 + col];
                float gv = acc[i][12 + jj] + brow[384 + col];
                long long idx = (long long)r * 128 + col;
                float cn = sigf(fv) * g_c[idx] + sigf(iv) * tanhf(gv);
                float hn = sigf(ov) * tanhf(cn);
                g_c[idx] = cn;
                g_h[idx] = hn;
                oseq[idx] = hn;
            }
        }
    }
}

// ---------------- host launcher ----------------
extern "C" void kernel_launch(void* const* d_in, const int* in_sizes, int n_in,
                              void* d_out, int out_size) {
    const float* h  = (const float*)d_in[0];
    const float* c  = (const float*)d_in[1];
    const void*  ei = d_in[2];
    const float* ea = (const float*)d_in[3];
    const float* Wi = (const float*)d_in[4];
    const float* bi = (const float*)d_in[5];
    const float* Wc = (const float*)d_in[6];
    const float* bc = (const float*)d_in[7];
    float* out = (float*)d_out;

    int n   = in_sizes[0] / 128;
    int E   = in_sizes[3];
    int seq = out_size / (n * 128);

    // resolve device-symbol addresses once (first call = correctness run, pre-capture)
    static float* p_Phc = nullptr;
    static float* p_base = nullptr;
    static float* p_h = nullptr;
    static float* p_c = nullptr;
    static float* p_z = nullptr;
    if (!p_Phc) {
        cudaGetSymbolAddress((void**)&p_Phc, g_Phc);
        cudaGetSymbolAddress((void**)&p_base, g_base);
        cudaGetSymbolAddress((void**)&p_h, g_h);
        cudaGetSymbolAddress((void**)&p_c, g_c);
        cudaGetSymbolAddress((void**)&p_z, g_z);
    }

    int nb256 = (n + 255) / 256;
    int eb256 = (E + 255) / 256;
    int gemm_blocks = (n + 31) / 32;
    int prop_blocks = (n * 32 + 255) / 256;

    // ---- graph setup (per launch; deterministic) ----
    k_init<<<nb256, 256>>>(n);
    k_detect<<<1, 128>>>((const unsigned int*)ei);
    k_build<<<eb256, 256>>>(ei, ea, E);
    k_dinv<<<nb256, 256>>>(n);
    k_scan<<<1, 1024>>>(n);
    k_scatter<<<eb256, 256>>>(ea, E);

    // ---- loop-invariant precompute ----
    k_prop<<<prop_blocks, 256>>>(h, 128, p_Phc, 256, n);        // P_h
    k_prop<<<prop_blocks, 256>>>(c, 128, p_Phc + 128, 256, n);  // P_c
    k_gemm_init<<<gemm_blocks, 256>>>(Wi, bi, n);               // -> g_h, g_c
    // base = P_h @ W_cell[:128,:] + b_cell
    k_gemm512<<<gemm_blocks, 256>>>(p_Phc, 256, Wc, bc, p_base, nullptr, n, 0);

    // ---- sequence ----
    for (int t = 0; t < seq; t++) {
        k_prop<<<prop_blocks, 256>>>(p_h, 128, p_z, 128, n);
        k_gemm512<<<gemm_blocks, 256>>>(p_z, 128, Wc + (long long)128 * 512, p_base,
                                        nullptr, out + (long long)t * n * 128, n, 1);
    }
}

// round 2
// speedup vs baseline: 1.3172x; 1.3172x over previous
#include <cuda_runtime.h>
#include <math.h>

#define MAXN 20000
#define MAXE 320000

// ---------------- device scratch (no allocs allowed) ----------------
__device__ int   g_is64;
__device__ int   g_src[MAXE];
__device__ int   g_dst[MAXE];
__device__ int   g_esrc[MAXE];
__device__ float g_ewn[MAXE];
__device__ float g_deg[MAXN];
__device__ float g_dinv[MAXN];
__device__ int   g_cnt[MAXN];
__device__ int   g_rowptr[MAXN + 1];
__device__ int   g_cursor[MAXN];
__device__ float g_Phc[MAXN * 256];          // [P_h | P_c]
__device__ float g_base[(long long)MAXN * 512];
__device__ float g_h[MAXN * 128];
__device__ float g_c[MAXN * 128];
__device__ float g_z[MAXN * 128];

// ---------------- f32x2 helpers ----------------
#define FMA2(a, x, w) asm("fma.rn.f32x2 %0, %1, %2, %0;" : "+l"(a) : "l"(x), "l"(w))

__device__ __forceinline__ unsigned long long pk2(float v) {
    unsigned long long r;
    asm("mov.b64 %0, {%1, %1};" : "=l"(r) : "f"(v));
    return r;
}
__device__ __forceinline__ void upk2(float& lo, float& hi, unsigned long long v) {
    asm("mov.b64 {%0, %1}, %2;" : "=f"(lo), "=f"(hi) : "l"(v));
}
__device__ __forceinline__ float tanhA(float x) {
    float r; asm("tanh.approx.f32 %0, %1;" : "=f"(r) : "f"(x)); return r;
}
__device__ __forceinline__ float sigA(float x) {
    return fmaf(tanhA(0.5f * x), 0.5f, 0.5f);
}

// ---------------- setup kernels ----------------
__global__ void k_init(int n) {
    int i = blockIdx.x * blockDim.x + threadIdx.x;
    if (i < n) { g_deg[i] = 0.f; g_cnt[i] = 0; }
    if (i == 0) g_is64 = 1;
}

// int64 values < 2^31 have zero high words; int32 edge data has random values
// at odd word positions. 128 odd words all zero => int64.
__global__ void k_detect(const unsigned int* __restrict__ w) {
    unsigned int v = w[2 * threadIdx.x + 1];
    if (v != 0u) g_is64 = 0;
}

__global__ void k_build(const void* __restrict__ ei, const float* __restrict__ ea, int E) {
    int e = blockIdx.x * blockDim.x + threadIdx.x;
    if (e >= E) return;
    int s, d;
    if (g_is64) {
        const long long* p = (const long long*)ei;
        s = (int)p[e]; d = (int)p[E + e];
    } else {
        const int* p = (const int*)ei;
        s = p[e]; d = p[E + e];
    }
    g_src[e] = s; g_dst[e] = d;
    atomicAdd(&g_deg[d], ea[e]);
    atomicAdd(&g_cnt[d], 1);
}

__global__ void k_dinv(int n) {
    int i = blockIdx.x * blockDim.x + threadIdx.x;
    if (i < n) g_dinv[i] = rsqrtf(g_deg[i] + 1.0f);
}

// single-block exclusive scan of g_cnt -> g_rowptr, g_cursor
__global__ void k_scan(int n) {
    __shared__ int s[1024];
    __shared__ int carry;
    if (threadIdx.x == 0) carry = 0;
    __syncthreads();
    for (int base = 0; base < n; base += 1024) {
        int i = base + threadIdx.x;
        int v = (i < n) ? g_cnt[i] : 0;
        s[threadIdx.x] = v;
        __syncthreads();
        for (int off = 1; off < 1024; off <<= 1) {
            int t = (threadIdx.x >= off) ? s[threadIdx.x - off] : 0;
            __syncthreads();
            s[threadIdx.x] += t;
            __syncthreads();
        }
        if (i < n) {
            int ex = carry + s[threadIdx.x] - v;
            g_rowptr[i] = ex;
            g_cursor[i] = ex;
        }
        __syncthreads();
        if (threadIdx.x == 0) carry += s[1023];
        __syncthreads();
    }
    if (threadIdx.x == 0) g_rowptr[n] = carry;
}

__global__ void k_scatter(const float* __restrict__ ea, int E) {
    int e = blockIdx.x * blockDim.x + threadIdx.x;
    if (e >= E) return;
    int s = g_src[e], d = g_dst[e];
    int pos = atomicAdd(&g_cursor[d], 1);
    g_esrc[pos] = s;
    g_ewn[pos] = g_dinv[s] * ea[e] * g_dinv[d];
}

// ---------------- sparse propagate: out[v] = sum_{e: dst=v} w_e * x[src_e] + dinv[v]^2 * x[v]
// one warp per node, 4 floats per lane (128 cols)
__global__ void k_prop(const float* __restrict__ x, int ldx,
                       float* __restrict__ out, int ldo, int n) {
    int v = (blockIdx.x * blockDim.x + threadIdx.x) >> 5;
    int lane = threadIdx.x & 31;
    if (v >= n) return;
    int beg = g_rowptr[v], end = g_rowptr[v + 1];
    float ax = 0.f, ay = 0.f, az = 0.f, aw = 0.f;
    int e = beg;
    for (; e + 1 < end; e += 2) {
        int s0 = g_esrc[e], s1 = g_esrc[e + 1];
        float w0 = g_ewn[e], w1 = g_ewn[e + 1];
        float4 v0 = __ldg((const float4*)(x + (long long)s0 * ldx) + lane);
        float4 v1 = __ldg((const float4*)(x + (long long)s1 * ldx) + lane);
        ax = fmaf(w0, v0.x, ax); ay = fmaf(w0, v0.y, ay);
        az = fmaf(w0, v0.z, az); aw = fmaf(w0, v0.w, aw);
        ax = fmaf(w1, v1.x, ax); ay = fmaf(w1, v1.y, ay);
        az = fmaf(w1, v1.z, az); aw = fmaf(w1, v1.w, aw);
    }
    if (e < end) {
        int s0 = g_esrc[e];
        float w0 = g_ewn[e];
        float4 v0 = __ldg((const float4*)(x + (long long)s0 * ldx) + lane);
        ax = fmaf(w0, v0.x, ax); ay = fmaf(w0, v0.y, ay);
        az = fmaf(w0, v0.z, az); aw = fmaf(w0, v0.w, aw);
    }
    float di = g_dinv[v];
    float w2 = di * di;
    float4 vv = __ldg((const float4*)(x + (long long)v * ldx) + lane);
    ax = fmaf(w2, vv.x, ax); ay = fmaf(w2, vv.y, ay);
    az = fmaf(w2, vv.z, az); aw = fmaf(w2, vv.w, aw);
    float4 o; o.x = ax; o.y = ay; o.z = az; o.w = aw;
    *((float4*)(out + (long long)v * ldo) + lane) = o;
}

// ---------------- init GEMM: states = elu(Phc[N,256] @ W_init[256,256] + b_init)
// h = states[:,:128], c = states[:,128:]
// 128 threads, 32 rows/block, 8 rows x 8 cols per thread (4 x f32x2 per row)
__global__ void __launch_bounds__(128, 3) k_gemm_init(const float* __restrict__ W,
                                                      const float* __restrict__ b, int n) {
    __shared__ float ws[16][256];
    __shared__ unsigned long long xs2[32][17];
    const int tid = threadIdx.x;
    const int tx = tid & 31;
    const int ty = tid >> 5;
    const int row0 = blockIdx.x * 32;

    unsigned long long acc[8][4];
#pragma unroll
    for (int i = 0; i < 8; i++)
#pragma unroll
        for (int q = 0; q < 4; q++) acc[i][q] = 0ull;

    for (int k0 = 0; k0 < 256; k0 += 16) {
        // ws: 16 x 256 floats, 128 threads -> 8 float4 each
#pragma unroll
        for (int it = 0; it < 8; it++) {
            int idx = tid + it * 128;      // 0..1023
            int r = idx >> 6, c4 = idx & 63;
            float4 v = __ldg((const float4*)(W + (long long)(k0 + r) * 256) + c4);
            *(float4*)&ws[r][c4 * 4] = v;
        }
        // xs2: row r = tid>>2, k-chunk (tid&3)*4
        {
            int r = tid >> 2, kk = (tid & 3) * 4;
            int gr = row0 + r;
            float4 v = make_float4(0.f, 0.f, 0.f, 0.f);
            if (gr < n) v = __ldg((const float4*)(g_Phc + (long long)gr * 256 + k0 + kk));
            xs2[r][kk + 0] = pk2(v.x); xs2[r][kk + 1] = pk2(v.y);
            xs2[r][kk + 2] = pk2(v.z); xs2[r][kk + 3] = pk2(v.w);
        }
        __syncthreads();
#pragma unroll
        for (int k = 0; k < 16; k++) {
            unsigned long long w2[4];
#pragma unroll
            for (int q = 0; q < 2; q++) {
                const unsigned long long* wp =
                    (const unsigned long long*)&ws[k][q * 128 + tx * 4];
                w2[2 * q] = wp[0]; w2[2 * q + 1] = wp[1];
            }
#pragma unroll
            for (int i = 0; i < 8; i++) {
                unsigned long long xx = xs2[ty + 4 * i][k];
#pragma unroll
                for (int q = 0; q < 4; q++) FMA2(acc[i][q], xx, w2[q]);
            }
        }
        __syncthreads();
    }

    float4 b0 = *(const float4*)&b[0 * 128 + 4 * tx];
    float4 b1 = *(const float4*)&b[1 * 128 + 4 * tx];
#pragma unroll
    for (int i = 0; i < 8; i++) {
        int r = row0 + ty + 4 * i;
        if (r >= n) continue;
        float v[8];
        upk2(v[0], v[1], acc[i][0]); upk2(v[2], v[3], acc[i][1]);
        upk2(v[4], v[5], acc[i][2]); upk2(v[6], v[7], acc[i][3]);
        v[0] += b0.x; v[1] += b0.y; v[2] += b0.z; v[3] += b0.w;
        v[4] += b1.x; v[5] += b1.y; v[6] += b1.z; v[7] += b1.w;
#pragma unroll
        for (int m = 0; m < 8; m++) v[m] = (v[m] > 0.f) ? v[m] : expm1f(v[m]);
        float4 oh; oh.x = v[0]; oh.y = v[1]; oh.z = v[2]; oh.w = v[3];
        float4 oc; oc.x = v[4]; oc.y = v[5]; oc.z = v[6]; oc.w = v[7];
        *(float4*)&g_h[(long long)r * 128 + 4 * tx] = oh;
        *(float4*)&g_c[(long long)r * 128 + 4 * tx] = oc;
    }
}

// ---------------- main GEMM: [n,128] @ W[128,512]
// 128 threads, 32 rows/block, 8 rows x 16 cols per thread (8 x f32x2 per row)
// thread cols: q*128 + 4*tx + {0..3} for q = 0..3  (q == LSTM gate)
// mode 0: out512 = acc + bias(aux[512])          (base precompute)
// mode 1: cc = acc + base(aux[n*512]); LSTM gates; update g_h/g_c; write oseq
__global__ void __launch_bounds__(128, 3) k_gemm512(const float* __restrict__ X, int ldx,
                                                    const float* __restrict__ W,
                                                    const float* __restrict__ aux,
                                                    float* __restrict__ o512,
                                                    float* __restrict__ oseq,
                                                    int n, int mode) {
    __shared__ float ws[16][512];
    __shared__ unsigned long long xs2[32][17];
    const int tid = threadIdx.x;
    const int tx = tid & 31;
    const int ty = tid >> 5;
    const int row0 = blockIdx.x * 32;

    unsigned long long acc[8][8];
#pragma unroll
    for (int i = 0; i < 8; i++)
#pragma unroll
        for (int q = 0; q < 8; q++) acc[i][q] = 0ull;

    for (int k0 = 0; k0 < 128; k0 += 16) {
        // ws: 16 x 512 floats, 128 threads -> 16 float4 each
#pragma unroll
        for (int it = 0; it < 16; it++) {
            int idx = tid + it * 128;        // 0..2047
            int r = idx >> 7, c4 = idx & 127;
            float4 v = __ldg((const float4*)(W + (long long)(k0 + r) * 512) + c4);
            *(float4*)&ws[r][c4 * 4] = v;
        }
        {
            int r = tid >> 2, kk = (tid & 3) * 4;
            int gr = row0 + r;
            float4 v = make_float4(0.f, 0.f, 0.f, 0.f);
            if (gr < n) v = __ldg((const float4*)(X + (long long)gr * ldx + k0 + kk));
            xs2[r][kk + 0] = pk2(v.x); xs2[r][kk + 1] = pk2(v.y);
            xs2[r][kk + 2] = pk2(v.z); xs2[r][kk + 3] = pk2(v.w);
        }
        __syncthreads();
#pragma unroll
        for (int k = 0; k < 16; k++) {
            unsigned long long w2[8];
#pragma unroll
            for (int q = 0; q < 4; q++) {
                const unsigned long long* wp =
                    (const unsigned long long*)&ws[k][q * 128 + tx * 4];
                w2[2 * q] = wp[0]; w2[2 * q + 1] = wp[1];
            }
#pragma unroll
            for (int i = 0; i < 8; i++) {
                unsigned long long xx = xs2[ty + 4 * i][k];
#pragma unroll
                for (int q = 0; q < 8; q++) FMA2(acc[i][q], xx, w2[q]);
            }
        }
        __syncthreads();
    }

    if (mode == 0) {
        float4 a0 = *(const float4*)&aux[0 * 128 + 4 * tx];
        float4 a1 = *(const float4*)&aux[1 * 128 + 4 * tx];
        float4 a2 = *(const float4*)&aux[2 * 128 + 4 * tx];
        float4 a3 = *(const float4*)&aux[3 * 128 + 4 * tx];
#pragma unroll
        for (int i = 0; i < 8; i++) {
            int r = row0 + ty + 4 * i;
            if (r >= n) continue;
            float v[16];
#pragma unroll
            for (int q = 0; q < 8; q++) upk2(v[2 * q], v[2 * q + 1], acc[i][q]);
            float4 o0, o1, o2, o3;
            o0.x = v[0] + a0.x;  o0.y = v[1] + a0.y;  o0.z = v[2] + a0.z;  o0.w = v[3] + a0.w;
            o1.x = v[4] + a1.x;  o1.y = v[5] + a1.y;  o1.z = v[6] + a1.z;  o1.w = v[7] + a1.w;
            o2.x = v[8] + a2.x;  o2.y = v[9] + a2.y;  o2.z = v[10] + a2.z; o2.w = v[11] + a2.w;
            o3.x = v[12] + a3.x; o3.y = v[13] + a3.y; o3.z = v[14] + a3.z; o3.w = v[15] + a3.w;
            float* orow = o512 + (long long)r * 512 + 4 * tx;
            *(float4*)&orow[0]   = o0;
            *(float4*)&orow[128] = o1;
            *(float4*)&orow[256] = o2;
            *(float4*)&orow[384] = o3;
        }
    } else {
#pragma unroll
        for (int i = 0; i < 8; i++) {
            int r = row0 + ty + 4 * i;
            if (r >= n) continue;
            float v[16];
#pragma unroll
            for (int q = 0; q < 8; q++) upk2(v[2 * q], v[2 * q + 1], acc[i][q]);
            const float* brow = aux + (long long)r * 512 + 4 * tx;
            float4 bi = *(const float4*)&brow[0];
            float4 bf = *(const float4*)&brow[128];
            float4 bo = *(const float4*)&brow[256];
            float4 bg = *(const float4*)&brow[384];
            long long cidx = (long long)r * 128 + 4 * tx;
            float4 cold = *(const float4*)&g_c[cidx];
            float iv[4] = {v[0] + bi.x, v[1] + bi.y, v[2] + bi.z, v[3] + bi.w};
            float fv[4] = {v[4] + bf.x, v[5] + bf.y, v[6] + bf.z, v[7] + bf.w};
            float ov[4] = {v[8] + bo.x, v[9] + bo.y, v[10] + bo.z, v[11] + bo.w};
            float gv[4] = {v[12] + bg.x, v[13] + bg.y, v[14] + bg.z, v[15] + bg.w};
            float co[4] = {cold.x, cold.y, cold.z, cold.w};
            float cn[4], hn[4];
#pragma unroll
            for (int m = 0; m < 4; m++) {
                cn[m] = sigA(fv[m]) * co[m] + sigA(iv[m]) * tanhA(gv[m]);
                hn[m] = sigA(ov[m]) * tanhA(cn[m]);
            }
            float4 oc; oc.x = cn[0]; oc.y = cn[1]; oc.z = cn[2]; oc.w = cn[3];
            float4 oh; oh.x = hn[0]; oh.y = hn[1]; oh.z = hn[2]; oh.w = hn[3];
            *(float4*)&g_c[cidx] = oc;
            *(float4*)&g_h[cidx] = oh;
            *(float4*)&oseq[cidx] = oh;
        }
    }
}

// ---------------- host launcher ----------------
extern "C" void kernel_launch(void* const* d_in, const int* in_sizes, int n_in,
                              void* d_out, int out_size) {
    const float* h  = (const float*)d_in[0];
    const float* c  = (const float*)d_in[1];
    const void*  ei = d_in[2];
    const float* ea = (const float*)d_in[3];
    const float* Wi = (const float*)d_in[4];
    const float* bi = (const float*)d_in[5];
    const float* Wc = (const float*)d_in[6];
    const float* bc = (const float*)d_in[7];
    float* out = (float*)d_out;

    int n   = in_sizes[0] / 128;
    int E   = in_sizes[3];
    int seq = out_size / (n * 128);

    // resolve device-symbol addresses once (first call = correctness run, pre-capture)
    static float* p_Phc = nullptr;
    static float* p_base = nullptr;
    static float* p_h = nullptr;
    static float* p_z = nullptr;
    if (!p_Phc) {
        cudaGetSymbolAddress((void**)&p_Phc, g_Phc);
        cudaGetSymbolAddress((void**)&p_base, g_base);
        cudaGetSymbolAddress((void**)&p_h, g_h);
        cudaGetSymbolAddress((void**)&p_z, g_z);
    }

    int nb256 = (n + 255) / 256;
    int eb256 = (E + 255) / 256;
    int gemm_blocks = (n + 31) / 32;
    int prop_blocks = (n * 32 + 255) / 256;

    // ---- graph setup (per launch; deterministic) ----
    k_init<<<nb256, 256>>>(n);
    k_detect<<<1, 128>>>((const unsigned int*)ei);
    k_build<<<eb256, 256>>>(ei, ea, E);
    k_dinv<<<nb256, 256>>>(n);
    k_scan<<<1, 1024>>>(n);
    k_scatter<<<eb256, 256>>>(ea, E);

    // ---- loop-invariant precompute ----
    k_prop<<<prop_blocks, 256>>>(h, 128, p_Phc, 256, n);        // P_h
    k_prop<<<prop_blocks, 256>>>(c, 128, p_Phc + 128, 256, n);  // P_c
    k_gemm_init<<<gemm_blocks, 128>>>(Wi, bi, n);               // -> g_h, g_c
    // base = P_h @ W_cell[:128,:] + b_cell
    k_gemm512<<<gemm_blocks, 128>>>(p_Phc, 256, Wc, bc, p_base, nullptr, n, 0);

    // ---- sequence ----
    for (int t = 0; t < seq; t++) {
        k_prop<<<prop_blocks, 256>>>(p_h, 128, p_z, 128, n);
        k_gemm512<<<gemm_blocks, 128>>>(p_z, 128, Wc + (long long)128 * 512, p_base,
                                        nullptr, out + (long long)t * n * 128, n, 1);
    }
}